// round 16
// baseline (speedup 1.0000x reference)
#include <cuda_runtime.h>
#include <cuda_bf16.h>
#include <math.h>
#include <stdint.h>

#define TT 256
#define OBS 512
#define HID 1024
#define MSG 128

typedef unsigned long long u64;

// ---- device scratch (static; no allocations) ----
// q' as A-fragment-linear: tile(16m x 16k) id = mt*8+kt, 256 bf16/tile
__device__ __align__(16) __nv_bfloat16 g_qh[HID * MSG];
__device__ __align__(16) __nv_bfloat16 g_ql[HID * MSG];
// h as B-fragment-linear per t: tile(8i x 16k) id = it*8+kt, 128 bf16/tile
__device__ __align__(16) __nv_bfloat16 g_Kh[TT * OBS * MSG];
__device__ __align__(16) __nv_bfloat16 g_Kl[TT * OBS * MSG];
__device__ float g_qf[HID * MSG];                              // q fp32 [m][j]
__device__ float g_c[HID];                                     // c[m] = q[m].bk
__device__ float g_x[TT * OBS];                                // normalized obs
__device__ float g_act[TT * OBS];                              // b_ih+b_hh + W_ih[:,1:]@a_t
__device__ float g_wih0[512];                                  // W_ih[:,0]
// W_hh as MMA A-fragment-linear images: [(mtw*8+kt)*32 + lane] -> uint4
__device__ __align__(16) uint4 g_WhiF[8192];                   // 128 KB
__device__ __align__(16) uint4 g_WloF[8192];                   // 128 KB

__device__ __forceinline__ float fsig(float x) {
    return 1.0f / (1.0f + __expf(-x));
}
__device__ __forceinline__ float ftanh(float x) {
    float t = __expf(-2.0f * fabsf(x));
    float r = (1.0f - t) / (1.0f + t);
    return copysignf(r, x);
}

__device__ __forceinline__ void mma_bf16(float* d, const uint32_t* a,
                                         uint32_t b0, uint32_t b1) {
    asm volatile(
        "mma.sync.aligned.m16n8k16.row.col.f32.bf16.bf16.f32 "
        "{%0,%1,%2,%3}, {%4,%5,%6,%7}, {%8,%9}, {%0,%1,%2,%3};"
        : "+f"(d[0]), "+f"(d[1]), "+f"(d[2]), "+f"(d[3])
        : "r"(a[0]), "r"(a[1]), "r"(a[2]), "r"(a[3]), "r"(b0), "r"(b1));
}

// ---------------------------------------------------------------------------
// setup: prep (normalize obs, action term, wih0) + q1 (q fp32) + wfrag
// all mutually independent -> one launch.  grid 512 x 256.
// ---------------------------------------------------------------------------
__global__ void setup_kernel(const float* __restrict__ obs,
                             const float* __restrict__ prev_act,
                             const float* __restrict__ in_shift,
                             const float* __restrict__ in_scale,
                             const float* __restrict__ W_ih,
                             const float* __restrict__ b_ih,
                             const float* __restrict__ b_hh,
                             const float* __restrict__ pe,
                             const float* __restrict__ Wq,
                             const float* __restrict__ bq,
                             const float* __restrict__ W_hh) {
    int idx = blockIdx.x * blockDim.x + threadIdx.x;  // 0..131071
    int i = idx & 511;
    int t = idx >> 9;

    // --- prep ---
    g_x[idx] = (obs[idx] - in_shift[i]) / (in_scale[i] + 1e-8f);
    {
        int j = i;
        float a = b_ih[j] + b_hh[j];
        const float* wr = W_ih + j * 33 + 1;
        const float* ar = prev_act + t * 32;
#pragma unroll
        for (int aa = 0; aa < 32; aa++) a = fmaf(wr[aa], ar[aa], a);
        g_act[idx] = a;
    }
    if (idx < 512) g_wih0[idx] = W_ih[idx * 33];

    // --- q1: q[m][j] fp32 ---
    {
        int m = idx >> 7, j = idx & 127;
        float acc = bq[j];
        const float* per = pe + m * 128;
        const float* wr = Wq + j * 128;
#pragma unroll 4
        for (int k = 0; k < 128; k++) acc = fmaf(per[k], wr[k], acc);
        g_qf[idx] = acc;
    }

    // --- wfrag (first 8192 threads) ---
    if (idx < 8192) {
        int lane = idx & 31;
        int tile = idx >> 5;
        int kt = tile & 7;
        int mtw = tile >> 3;
        int g = lane >> 2, tg = lane & 3;
        int jb = mtw * 16;
        int k0 = kt * 16 + tg * 2;

        uint32_t hi[4], lo[4];
#pragma unroll
        for (int r = 0; r < 4; r++) {
            int row = jb + g + (r & 1) * 8;
            int col = k0 + (r >> 1) * 8;
            float w0 = W_hh[row * 128 + col];
            float w1 = W_hh[row * 128 + col + 1];
            __nv_bfloat16 h0 = __float2bfloat16(w0);
            __nv_bfloat16 h1 = __float2bfloat16(w1);
            __nv_bfloat16 l0 = __float2bfloat16(w0 - __bfloat162float(h0));
            __nv_bfloat16 l1 = __float2bfloat16(w1 - __bfloat162float(h1));
            hi[r] = (uint32_t)*(uint16_t*)&h0 | ((uint32_t)*(uint16_t*)&h1 << 16);
            lo[r] = (uint32_t)*(uint16_t*)&l0 | ((uint32_t)*(uint16_t*)&l1 << 16);
        }
        g_WhiF[idx] = make_uint4(hi[0], hi[1], hi[2], hi[3]);
        g_WloF[idx] = make_uint4(lo[0], lo[1], lo[2], lo[3]);
    }
}

// ---------------------------------------------------------------------------
// q2: q'[m][p] -> A-fragment-linear hi/lo; c[m] = q[m].bk
// ---------------------------------------------------------------------------
__global__ void q2_kernel(const float* __restrict__ Wk,
                          const float* __restrict__ bk) {
    int idx = blockIdx.x * blockDim.x + threadIdx.x;  // 131072
    int m = idx >> 7, p = idx & 127;
    const float* qf = g_qf + m * 128;
    float acc = 0.0f;
#pragma unroll 4
    for (int j = 0; j < 128; j++) acc = fmaf(qf[j], Wk[j * 128 + p], acc);

    __nv_bfloat16 hb = __float2bfloat16(acc);
    __nv_bfloat16 lb = __float2bfloat16(acc - __bfloat162float(hb));
    {
        int mt = m >> 4, mloc = m & 15;
        int kt = p >> 4, kloc = p & 15;
        int lane = (mloc & 7) * 4 + ((kloc >> 1) & 3);
        int r = (mloc >> 3) + 2 * (kloc >> 3);
        int a = ((mt * 8 + kt) << 8) + lane * 8 + r * 2 + (kloc & 1);
        g_qh[a] = hb;
        g_ql[a] = lb;
    }

    if (p == 0) {
        float c = 0.0f;
#pragma unroll 4
        for (int j = 0; j < 128; j++) c = fmaf(qf[j], bk[j], c);
        g_c[m] = c;
    }
}

// ---------------------------------------------------------------------------
// LSTM via HMMA gate GEMM: 128 CTAs x 4 neurons, 512 threads (16 warps).
// 4 independent accumulator chains (hi/lo split per m-tile) for MMA ILP.
// ---------------------------------------------------------------------------
#define GTP 516
#define WLO_B 0
#define GT_B  131072
#define HHI_B (GT_B + 8320)
#define HLO_B (HHI_B + 2176)
#define ACT_B (HLO_B + 2176)
#define WIH_B (ACT_B + 4096)
#define SS_B  (WIH_B + 2048)
#define LSTM_SMEM (SS_B + 32)

__global__ __launch_bounds__(512, 1) void lstm_kernel() {
    extern __shared__ char smc[];
    uint4* wlo_s = (uint4*)(smc + WLO_B);                // 8192 uint4
    float* gt_s  = (float*)(smc + GT_B);                 // 4 x GTP
    __nv_bfloat16* hhi = (__nv_bfloat16*)(smc + HHI_B);  // 8 x 136
    __nv_bfloat16* hlo = (__nv_bfloat16*)(smc + HLO_B);
    float* act_s = (float*)(smc + ACT_B);                // 2 x 512
    float* wih_s = (float*)(smc + WIH_B);                // 512
    float* s_s   = (float*)(smc + SS_B);                 // 2 x 4

    int tid = threadIdx.x;                               // 0..511
    int lane = tid & 31, w = tid >> 5;
    int g = lane >> 2, tg = lane & 3;
    int n0 = blockIdx.x * 4;
    int pn = tid >> 7, pj = tid & 127;                   // pointwise mapping

    // one-time staging
#pragma unroll
    for (int f = 0; f < 16; f++) wlo_s[tid + f * 512] = g_WloF[tid + f * 512];
    uint4 whi[16];
#pragma unroll
    for (int mt = 0; mt < 2; mt++)
#pragma unroll
        for (int kt = 0; kt < 8; kt++)
            whi[mt * 8 + kt] = g_WhiF[((w * 2 + mt) * 8 + kt) * 32 + lane];
    for (int f = tid; f < 8 * 136; f += 512) { hhi[f] = __float2bfloat16(0.f); hlo[f] = __float2bfloat16(0.f); }
    wih_s[tid] = g_wih0[tid];
    act_s[tid] = g_act[tid];
    if (tid < 4) s_s[tid] = g_x[n0 + tid];
    float c_r = 0.0f;

    // fragment-linear write address for h
    int w_it = (n0 + pn) >> 3;
    int w_kt = pj >> 4;
    int w_kloc = pj & 15;
    int w_lane = ((n0 + pn) & 7) * 4 + ((w_kloc >> 1) & 3);
    int w_off = ((w_it * 8 + w_kt) << 7) + w_lane * 4 + (w_kloc >> 3) * 2 + (w_kloc & 1);
    __syncthreads();

    for (int t = 0; t < TT; t++) {
        int tn = (t + 1 < TT) ? t + 1 : t;
        float act_n = g_act[tn * 512 + tid];
        float s_n = (tid < 4) ? g_x[tn * 512 + n0 + tid] : 0.0f;

        // ---- gate GEMM: 4 independent HMMA chains ----
        float a0h[4] = {0, 0, 0, 0}, a0l[4] = {0, 0, 0, 0};
        float a1h[4] = {0, 0, 0, 0}, a1l[4] = {0, 0, 0, 0};
#pragma unroll
        for (int kt = 0; kt < 8; kt++) {
            int ka = kt * 16 + tg * 2;
            uint32_t bh0 = *(const uint32_t*)&hhi[g * 136 + ka];
            uint32_t bh1 = *(const uint32_t*)&hhi[g * 136 + ka + 8];
            uint32_t bl0 = *(const uint32_t*)&hlo[g * 136 + ka];
            uint32_t bl1 = *(const uint32_t*)&hlo[g * 136 + ka + 8];
            {
                uint4 wv = whi[kt];
                uint32_t a[4] = {wv.x, wv.y, wv.z, wv.w};
                mma_bf16(a0h, a, bh0, bh1);
                mma_bf16(a0l, a, bl0, bl1);
                uint4 wl = wlo_s[((w * 2 + 0) * 8 + kt) * 32 + lane];
                uint32_t al[4] = {wl.x, wl.y, wl.z, wl.w};
                mma_bf16(a0l, al, bh0, bh1);
            }
            {
                uint4 wv = whi[8 + kt];
                uint32_t a[4] = {wv.x, wv.y, wv.z, wv.w};
                mma_bf16(a1h, a, bh0, bh1);
                mma_bf16(a1l, a, bl0, bl1);
                uint4 wl = wlo_s[((w * 2 + 1) * 8 + kt) * 32 + lane];
                uint32_t al[4] = {wl.x, wl.y, wl.z, wl.w};
                mma_bf16(a1l, al, bh0, bh1);
            }
        }
        if (tg < 2) {
            int j0 = w * 32 + g;
            gt_s[(tg * 2) * GTP + j0]          = a0h[0] + a0l[0];
            gt_s[(tg * 2 + 1) * GTP + j0]      = a0h[1] + a0l[1];
            gt_s[(tg * 2) * GTP + j0 + 8]      = a0h[2] + a0l[2];
            gt_s[(tg * 2 + 1) * GTP + j0 + 8]  = a0h[3] + a0l[3];
            int j1 = j0 + 16;
            gt_s[(tg * 2) * GTP + j1]          = a1h[0] + a1l[0];
            gt_s[(tg * 2 + 1) * GTP + j1]      = a1h[1] + a1l[1];
            gt_s[(tg * 2) * GTP + j1 + 8]      = a1h[2] + a1l[2];
            gt_s[(tg * 2 + 1) * GTP + j1 + 8]  = a1h[3] + a1l[3];
        }
        act_s[((t + 1) & 1) * 512 + tid] = act_n;
        if (tid < 4) s_s[((t + 1) & 1) * 4 + tid] = s_n;
        __syncthreads();

        // ---- pointwise (torch gate order i,f,g,o) ----
        {
            const float* ab = act_s + (t & 1) * 512;
            float sv = s_s[(t & 1) * 4 + pn];
            float gv[4];
#pragma unroll
            for (int e = 0; e < 4; e++) {
                int gi = e * 128 + pj;
                gv[e] = gt_s[pn * GTP + gi] + ab[gi] + sv * wih_s[gi];
            }
            float c = fsig(gv[1]) * c_r + fsig(gv[0]) * ftanh(gv[2]);
            float h = fsig(gv[3]) * ftanh(c);
            c_r = c;
            __nv_bfloat16 hb = __float2bfloat16(h);
            __nv_bfloat16 lb = __float2bfloat16(h - __bfloat162float(hb));
            hhi[pn * 136 + pj] = hb;
            hlo[pn * 136 + pj] = lb;
            g_Kh[(size_t)t * 65536 + w_off] = hb;
            g_Kl[(size_t)t * 65536 + w_off] = lb;
        }
        __syncthreads();
    }
}

// ---------------------------------------------------------------------------
// Attention via mma.sync, fragment-linear smem, SPLIT accumulator chains.
// CTA = 64 m x 512 i, 4 chunks of 128 i. ~99KB smem -> 2 CTAs/SM.
// ---------------------------------------------------------------------------
#define QFH_B 0
#define QFL_B 16384
#define KFH_B 32768
#define KFL_B 65536
#define SX_B  98304
#define PART_B 100352
#define ATTN_SMEM (PART_B + 1024)

__global__ __launch_bounds__(512) void attn_kernel(float* __restrict__ out) {
    extern __shared__ char smc[];
    __nv_bfloat16* qfh = (__nv_bfloat16*)(smc + QFH_B);  // 32 A-tiles
    __nv_bfloat16* qfl = (__nv_bfloat16*)(smc + QFL_B);
    __nv_bfloat16* kfh = (__nv_bfloat16*)(smc + KFH_B);  // 128 B-tiles
    __nv_bfloat16* kfl = (__nv_bfloat16*)(smc + KFL_B);
    float* s_s  = (float*)(smc + SX_B);                  // 512 floats
    float* part = (float*)(smc + PART_B);                // 256 floats

    int tid = threadIdx.x;
    int warp = tid >> 5;
    int lane = tid & 31;
    int wband = warp >> 2;   // 0..3 : m band (16 rows)
    int iq    = warp & 3;    // 0..3 : i quarter (32 i = 4 B-tiles)
    int g  = lane >> 2;
    int tg = lane & 3;
    int m0 = wband * 16;
    int mq = blockIdx.x;     // 0..15
    int t  = blockIdx.y;     // 0..255

    float c0 = g_c[mq * 64 + m0 + g];
    float c1 = g_c[mq * 64 + m0 + g + 8];

    {
        const float4* sh = (const float4*)&g_qh[(size_t)mq * 8192];
        const float4* sl = (const float4*)&g_ql[(size_t)mq * 8192];
        float4* dh = (float4*)qfh;
        float4* dl = (float4*)qfl;
#pragma unroll
        for (int f = 0; f < 2; f++) {
            dh[tid + f * 512] = sh[tid + f * 512];
            dl[tid + f * 512] = sl[tid + f * 512];
        }
        const float4* sx = (const float4*)&g_x[t * 512];
        if (tid < 128) ((float4*)s_s)[tid] = sx[tid];
    }

    float pr0 = 0.0f, pr1 = 0.0f;
    const float inv = 0.0883883476483184f;  // 1/sqrt(128)

#pragma unroll 1
    for (int c = 0; c < 4; c++) {
        if (c > 0) __syncthreads();
        {
            const float4* sh = (const float4*)&g_Kh[(size_t)t * 65536 + (size_t)c * 16384];
            const float4* sl = (const float4*)&g_Kl[(size_t)t * 65536 + (size_t)c * 16384];
            float4* dh = (float4*)kfh;
            float4* dl = (float4*)kfl;
#pragma unroll
            for (int f = 0; f < 4; f++) {
                dh[tid + f * 512] = sh[tid + f * 512];
                dl[tid + f * 512] = sl[tid + f * 512];
            }
        }
        __syncthreads();

        float accH[4][4], accL[4][4];
#pragma unroll
        for (int nt = 0; nt < 4; nt++)
#pragma unroll
            for (int e = 0; e < 4; e++) { accH[nt][e] = 0.0f; accL[nt][e] = 0.0f; }

#pragma unroll 1
        for (int kk = 0; kk < 8; kk++) {
            uint4 AH = *(const uint4*)&qfh[((wband * 8 + kk) << 8) + lane * 8];
            uint4 AL = *(const uint4*)&qfl[((wband * 8 + kk) << 8) + lane * 8];
            uint32_t ah[4] = {AH.x, AH.y, AH.z, AH.w};
            uint32_t al[4] = {AL.x, AL.y, AL.z, AL.w};
#pragma unroll
            for (int nt = 0; nt < 4; nt++) {
                int tb = (((iq * 4 + nt) * 8 + kk) << 7) + lane * 4;
                uint2 BH = *(const uint2*)&kfh[tb];
                uint2 BL = *(const uint2*)&kfl[tb];
                mma_bf16(accH[nt], ah, BH.x, BH.y);   // hi*hi  (chain 1)
                mma_bf16(accL[nt], ah, BL.x, BL.y);   // hi*lo  (chain 2)
                mma_bf16(accL[nt], al, BH.x, BH.y);   // lo*hi  (chain 2)
            }
        }

        // epilogue: tanh((scoreH + scoreL + c[m]) * inv) * s[i]
#pragma unroll
        for (int nt = 0; nt < 4; nt++) {
            int i0 = c * 128 + iq * 32 + nt * 8 + tg * 2;
            float sv0 = s_s[i0], sv1 = s_s[i0 + 1];
            pr0 = fmaf(ftanh((accH[nt][0] + accL[nt][0] + c0) * inv), sv0, pr0);
            pr0 = fmaf(ftanh((accH[nt][1] + accL[nt][1] + c0) * inv), sv1, pr0);
            pr1 = fmaf(ftanh((accH[nt][2] + accL[nt][2] + c1) * inv), sv0, pr1);
            pr1 = fmaf(ftanh((accH[nt][3] + accL[nt][3] + c1) * inv), sv1, pr1);
        }
    }

    pr0 += __shfl_xor_sync(0xffffffffu, pr0, 1);
    pr0 += __shfl_xor_sync(0xffffffffu, pr0, 2);
    pr1 += __shfl_xor_sync(0xffffffffu, pr1, 1);
    pr1 += __shfl_xor_sync(0xffffffffu, pr1, 2);
    if (tg == 0) {
        part[iq * 64 + m0 + g]     = pr0;
        part[iq * 64 + m0 + g + 8] = pr1;
    }
    __syncthreads();
    if (tid < 64)
        out[t * 1024 + mq * 64 + tid] =
            ftanh(part[tid] + part[64 + tid] + part[128 + tid] + part[192 + tid]);
}

// ---------------------------------------------------------------------------
extern "C" void kernel_launch(void* const* d_in, const int* in_sizes, int n_in,
                              void* d_out, int out_size) {
    const float* obs      = (const float*)d_in[0];
    const float* prev_act = (const float*)d_in[1];
    const float* in_shift = (const float*)d_in[2];
    const float* in_scale = (const float*)d_in[3];
    const float* pe       = (const float*)d_in[4];
    const float* W_ih     = (const float*)d_in[5];
    const float* b_ih     = (const float*)d_in[6];
    const float* W_hh     = (const float*)d_in[7];
    const float* b_hh     = (const float*)d_in[8];
    const float* Wq       = (const float*)d_in[9];
    const float* bq       = (const float*)d_in[10];
    const float* Wk       = (const float*)d_in[11];
    const float* bk       = (const float*)d_in[12];
    float* out = (float*)d_out;

    cudaFuncSetAttribute(attn_kernel, cudaFuncAttributeMaxDynamicSharedMemorySize,
                         ATTN_SMEM);
    cudaFuncSetAttribute(lstm_kernel, cudaFuncAttributeMaxDynamicSharedMemorySize,
                         LSTM_SMEM);

    setup_kernel<<<512, 256>>>(obs, prev_act, in_shift, in_scale,
                               W_ih, b_ih, b_hh, pe, Wq, bq, W_hh);
    q2_kernel<<<512, 256>>>(Wk, bk);
    lstm_kernel<<<128, 512, LSTM_SMEM>>>();
    dim3 ga(16, 256);
    attn_kernel<<<ga, 512, ATTN_SMEM>>>(out);
}

// round 17
// speedup vs baseline: 1.1338x; 1.1338x over previous
#include <cuda_runtime.h>
#include <cuda_bf16.h>
#include <math.h>
#include <stdint.h>

#define TT 256
#define OBS 512
#define HID 1024
#define MSG 128

typedef unsigned long long u64;

// ---- device scratch (static; no allocations) ----
// q' as A-fragment-linear: tile(16m x 16k) id = mt*8+kt, 256 bf16/tile
__device__ __align__(16) __nv_bfloat16 g_qh[HID * MSG];
__device__ __align__(16) __nv_bfloat16 g_ql[HID * MSG];
// h as B-fragment-linear per t: tile(8i x 16k) id = it*8+kt, 128 bf16/tile
__device__ __align__(16) __nv_bfloat16 g_Kh[TT * OBS * MSG];
__device__ __align__(16) __nv_bfloat16 g_Kl[TT * OBS * MSG];
__device__ float g_qf[HID * MSG];                              // q fp32 [m][j]
__device__ float g_c[HID];                                     // c[m] = q[m].bk
__device__ float g_x[TT * OBS];                                // normalized obs
__device__ float g_act[TT * OBS];                              // b_ih+b_hh + W_ih[:,1:]@a_t
__device__ float g_wih0[512];                                  // W_ih[:,0]
// W_hh as MMA A-fragment-linear images: [(mtw*8+kt)*32 + lane] -> uint4
__device__ __align__(16) uint4 g_WhiF[8192];                   // 128 KB
__device__ __align__(16) uint4 g_WloF[8192];                   // 128 KB

__device__ __forceinline__ float fsig(float x) {
    return __fdividef(1.0f, 1.0f + __expf(-x));
}
__device__ __forceinline__ float ftanh(float x) {
    float t = __expf(-2.0f * fabsf(x));
    float r = __fdividef(1.0f - t, 1.0f + t);
    return copysignf(r, x);
}

__device__ __forceinline__ void mma_bf16(float* d, const uint32_t* a,
                                         uint32_t b0, uint32_t b1) {
    asm volatile(
        "mma.sync.aligned.m16n8k16.row.col.f32.bf16.bf16.f32 "
        "{%0,%1,%2,%3}, {%4,%5,%6,%7}, {%8,%9}, {%0,%1,%2,%3};"
        : "+f"(d[0]), "+f"(d[1]), "+f"(d[2]), "+f"(d[3])
        : "r"(a[0]), "r"(a[1]), "r"(a[2]), "r"(a[3]), "r"(b0), "r"(b1));
}

// ---------------------------------------------------------------------------
// setup: prep (normalize obs, action term, wih0) + q1 (q fp32) + wfrag
// ---------------------------------------------------------------------------
__global__ void setup_kernel(const float* __restrict__ obs,
                             const float* __restrict__ prev_act,
                             const float* __restrict__ in_shift,
                             const float* __restrict__ in_scale,
                             const float* __restrict__ W_ih,
                             const float* __restrict__ b_ih,
                             const float* __restrict__ b_hh,
                             const float* __restrict__ pe,
                             const float* __restrict__ Wq,
                             const float* __restrict__ bq,
                             const float* __restrict__ W_hh) {
    int idx = blockIdx.x * blockDim.x + threadIdx.x;  // 0..131071
    int i = idx & 511;
    int t = idx >> 9;

    // --- prep ---
    g_x[idx] = (obs[idx] - in_shift[i]) / (in_scale[i] + 1e-8f);
    {
        int j = i;
        float a = b_ih[j] + b_hh[j];
        const float* wr = W_ih + j * 33 + 1;
        const float* ar = prev_act + t * 32;
#pragma unroll
        for (int aa = 0; aa < 32; aa++) a = fmaf(wr[aa], ar[aa], a);
        g_act[idx] = a;
    }
    if (idx < 512) g_wih0[idx] = W_ih[idx * 33];

    // --- q1: q[m][j] fp32 ---
    {
        int m = idx >> 7, j = idx & 127;
        float acc = bq[j];
        const float* per = pe + m * 128;
        const float* wr = Wq + j * 128;
#pragma unroll 4
        for (int k = 0; k < 128; k++) acc = fmaf(per[k], wr[k], acc);
        g_qf[idx] = acc;
    }

    // --- wfrag (first 8192 threads) ---
    if (idx < 8192) {
        int lane = idx & 31;
        int tile = idx >> 5;
        int kt = tile & 7;
        int mtw = tile >> 3;
        int g = lane >> 2, tg = lane & 3;
        int jb = mtw * 16;
        int k0 = kt * 16 + tg * 2;

        uint32_t hi[4], lo[4];
#pragma unroll
        for (int r = 0; r < 4; r++) {
            int row = jb + g + (r & 1) * 8;
            int col = k0 + (r >> 1) * 8;
            float w0 = W_hh[row * 128 + col];
            float w1 = W_hh[row * 128 + col + 1];
            __nv_bfloat16 h0 = __float2bfloat16(w0);
            __nv_bfloat16 h1 = __float2bfloat16(w1);
            __nv_bfloat16 l0 = __float2bfloat16(w0 - __bfloat162float(h0));
            __nv_bfloat16 l1 = __float2bfloat16(w1 - __bfloat162float(h1));
            hi[r] = (uint32_t)*(uint16_t*)&h0 | ((uint32_t)*(uint16_t*)&h1 << 16);
            lo[r] = (uint32_t)*(uint16_t*)&l0 | ((uint32_t)*(uint16_t*)&l1 << 16);
        }
        g_WhiF[idx] = make_uint4(hi[0], hi[1], hi[2], hi[3]);
        g_WloF[idx] = make_uint4(lo[0], lo[1], lo[2], lo[3]);
    }
}

// ---------------------------------------------------------------------------
// q2: q'[m][p] -> A-fragment-linear hi/lo; c[m] = q[m].bk
// ---------------------------------------------------------------------------
__global__ void q2_kernel(const float* __restrict__ Wk,
                          const float* __restrict__ bk) {
    int idx = blockIdx.x * blockDim.x + threadIdx.x;  // 131072
    int m = idx >> 7, p = idx & 127;
    const float* qf = g_qf + m * 128;
    float acc = 0.0f;
#pragma unroll 4
    for (int j = 0; j < 128; j++) acc = fmaf(qf[j], Wk[j * 128 + p], acc);

    __nv_bfloat16 hb = __float2bfloat16(acc);
    __nv_bfloat16 lb = __float2bfloat16(acc - __bfloat162float(hb));
    {
        int mt = m >> 4, mloc = m & 15;
        int kt = p >> 4, kloc = p & 15;
        int lane = (mloc & 7) * 4 + ((kloc >> 1) & 3);
        int r = (mloc >> 3) + 2 * (kloc >> 3);
        int a = ((mt * 8 + kt) << 8) + lane * 8 + r * 2 + (kloc & 1);
        g_qh[a] = hb;
        g_ql[a] = lb;
    }

    if (p == 0) {
        float c = 0.0f;
#pragma unroll 4
        for (int j = 0; j < 128; j++) c = fmaf(qf[j], bk[j], c);
        g_c[m] = c;
    }
}

// ---------------------------------------------------------------------------
// LSTM via HMMA gate GEMM: 128 CTAs x 4 neurons, 512 threads (16 warps).
// (R15 version: 2 accumulator chains per m-tile)
// ---------------------------------------------------------------------------
#define GTP 516
#define WLO_B 0
#define GT_B  131072
#define HHI_B (GT_B + 8320)
#define HLO_B (HHI_B + 2176)
#define ACT_B (HLO_B + 2176)
#define WIH_B (ACT_B + 4096)
#define SS_B  (WIH_B + 2048)
#define LSTM_SMEM (SS_B + 32)

__global__ __launch_bounds__(512, 1) void lstm_kernel() {
    extern __shared__ char smc[];
    uint4* wlo_s = (uint4*)(smc + WLO_B);                // 8192 uint4
    float* gt_s  = (float*)(smc + GT_B);                 // 4 x GTP
    __nv_bfloat16* hhi = (__nv_bfloat16*)(smc + HHI_B);  // 8 x 136
    __nv_bfloat16* hlo = (__nv_bfloat16*)(smc + HLO_B);
    float* act_s = (float*)(smc + ACT_B);                // 2 x 512
    float* wih_s = (float*)(smc + WIH_B);                // 512
    float* s_s   = (float*)(smc + SS_B);                 // 2 x 4

    int tid = threadIdx.x;                               // 0..511
    int lane = tid & 31, w = tid >> 5;
    int g = lane >> 2, tg = lane & 3;
    int n0 = blockIdx.x * 4;
    int pn = tid >> 7, pj = tid & 127;                   // pointwise mapping

    // one-time staging
#pragma unroll
    for (int f = 0; f < 16; f++) wlo_s[tid + f * 512] = g_WloF[tid + f * 512];
    uint4 whi[16];
#pragma unroll
    for (int mt = 0; mt < 2; mt++)
#pragma unroll
        for (int kt = 0; kt < 8; kt++)
            whi[mt * 8 + kt] = g_WhiF[((w * 2 + mt) * 8 + kt) * 32 + lane];
    for (int f = tid; f < 8 * 136; f += 512) { hhi[f] = __float2bfloat16(0.f); hlo[f] = __float2bfloat16(0.f); }
    wih_s[tid] = g_wih0[tid];
    act_s[tid] = g_act[tid];
    if (tid < 4) s_s[tid] = g_x[n0 + tid];
    float c_r = 0.0f;

    // fragment-linear write address for h
    int w_it = (n0 + pn) >> 3;
    int w_kt = pj >> 4;
    int w_kloc = pj & 15;
    int w_lane = ((n0 + pn) & 7) * 4 + ((w_kloc >> 1) & 3);
    int w_off = ((w_it * 8 + w_kt) << 7) + w_lane * 4 + (w_kloc >> 3) * 2 + (w_kloc & 1);
    __syncthreads();

    for (int t = 0; t < TT; t++) {
        int tn = (t + 1 < TT) ? t + 1 : t;
        float act_n = g_act[tn * 512 + tid];
        float s_n = (tid < 4) ? g_x[tn * 512 + n0 + tid] : 0.0f;

        // ---- gate GEMM: D[j 32][n 8] per warp, K=128 over 8 ktiles ----
        float acc0[4] = {0, 0, 0, 0};
        float acc1[4] = {0, 0, 0, 0};
#pragma unroll
        for (int kt = 0; kt < 8; kt++) {
            int ka = kt * 16 + tg * 2;
            uint32_t bh0 = *(const uint32_t*)&hhi[g * 136 + ka];
            uint32_t bh1 = *(const uint32_t*)&hhi[g * 136 + ka + 8];
            uint32_t bl0 = *(const uint32_t*)&hlo[g * 136 + ka];
            uint32_t bl1 = *(const uint32_t*)&hlo[g * 136 + ka + 8];
            {
                uint4 wv = whi[kt];
                uint32_t a[4] = {wv.x, wv.y, wv.z, wv.w};
                mma_bf16(acc0, a, bh0, bh1);
                mma_bf16(acc0, a, bl0, bl1);
                uint4 wl = wlo_s[((w * 2 + 0) * 8 + kt) * 32 + lane];
                uint32_t al[4] = {wl.x, wl.y, wl.z, wl.w};
                mma_bf16(acc0, al, bh0, bh1);
            }
            {
                uint4 wv = whi[8 + kt];
                uint32_t a[4] = {wv.x, wv.y, wv.z, wv.w};
                mma_bf16(acc1, a, bh0, bh1);
                mma_bf16(acc1, a, bl0, bl1);
                uint4 wl = wlo_s[((w * 2 + 1) * 8 + kt) * 32 + lane];
                uint32_t al[4] = {wl.x, wl.y, wl.z, wl.w};
                mma_bf16(acc1, al, bh0, bh1);
            }
        }
        if (tg < 2) {
            int j0 = w * 32 + g;
            gt_s[(tg * 2) * GTP + j0]          = acc0[0];
            gt_s[(tg * 2 + 1) * GTP + j0]      = acc0[1];
            gt_s[(tg * 2) * GTP + j0 + 8]      = acc0[2];
            gt_s[(tg * 2 + 1) * GTP + j0 + 8]  = acc0[3];
            int j1 = j0 + 16;
            gt_s[(tg * 2) * GTP + j1]          = acc1[0];
            gt_s[(tg * 2 + 1) * GTP + j1]      = acc1[1];
            gt_s[(tg * 2) * GTP + j1 + 8]      = acc1[2];
            gt_s[(tg * 2 + 1) * GTP + j1 + 8]  = acc1[3];
        }
        act_s[((t + 1) & 1) * 512 + tid] = act_n;
        if (tid < 4) s_s[((t + 1) & 1) * 4 + tid] = s_n;
        __syncthreads();

        // ---- pointwise (torch gate order i,f,g,o) ----
        {
            const float* ab = act_s + (t & 1) * 512;
            float sv = s_s[(t & 1) * 4 + pn];
            float gv[4];
#pragma unroll
            for (int e = 0; e < 4; e++) {
                int gi = e * 128 + pj;
                gv[e] = gt_s[pn * GTP + gi] + ab[gi] + sv * wih_s[gi];
            }
            float c = fsig(gv[1]) * c_r + fsig(gv[0]) * ftanh(gv[2]);
            float h = fsig(gv[3]) * ftanh(c);
            c_r = c;
            __nv_bfloat16 hb = __float2bfloat16(h);
            __nv_bfloat16 lb = __float2bfloat16(h - __bfloat162float(hb));
            hhi[pn * 136 + pj] = hb;
            hlo[pn * 136 + pj] = lb;
            g_Kh[(size_t)t * 65536 + w_off] = hb;
            g_Kl[(size_t)t * 65536 + w_off] = lb;
        }
        __syncthreads();
    }
}

// ---------------------------------------------------------------------------
// Attention via mma.sync, fragment-linear smem (R15 version, single chains).
// CTA = 64 m x 512 i, 4 chunks of 128 i. ~99KB smem -> 2 CTAs/SM.
// ---------------------------------------------------------------------------
#define QFH_B 0
#define QFL_B 16384
#define KFH_B 32768
#define KFL_B 65536
#define SX_B  98304
#define PART_B 100352
#define ATTN_SMEM (PART_B + 1024)

__global__ __launch_bounds__(512) void attn_kernel(float* __restrict__ out) {
    extern __shared__ char smc[];
    __nv_bfloat16* qfh = (__nv_bfloat16*)(smc + QFH_B);  // 32 A-tiles
    __nv_bfloat16* qfl = (__nv_bfloat16*)(smc + QFL_B);
    __nv_bfloat16* kfh = (__nv_bfloat16*)(smc + KFH_B);  // 128 B-tiles
    __nv_bfloat16* kfl = (__nv_bfloat16*)(smc + KFL_B);
    float* s_s  = (float*)(smc + SX_B);                  // 512 floats
    float* part = (float*)(smc + PART_B);                // 256 floats

    int tid = threadIdx.x;
    int warp = tid >> 5;
    int lane = tid & 31;
    int wband = warp >> 2;   // 0..3 : m band (16 rows)
    int iq    = warp & 3;    // 0..3 : i quarter (32 i = 4 B-tiles)
    int g  = lane >> 2;
    int tg = lane & 3;
    int m0 = wband * 16;
    int mq = blockIdx.x;     // 0..15
    int t  = blockIdx.y;     // 0..255

    float c0 = g_c[mq * 64 + m0 + g];
    float c1 = g_c[mq * 64 + m0 + g + 8];

    {
        const float4* sh = (const float4*)&g_qh[(size_t)mq * 8192];
        const float4* sl = (const float4*)&g_ql[(size_t)mq * 8192];
        float4* dh = (float4*)qfh;
        float4* dl = (float4*)qfl;
#pragma unroll
        for (int f = 0; f < 2; f++) {
            dh[tid + f * 512] = sh[tid + f * 512];
            dl[tid + f * 512] = sl[tid + f * 512];
        }
        const float4* sx = (const float4*)&g_x[t * 512];
        if (tid < 128) ((float4*)s_s)[tid] = sx[tid];
    }

    float pr0 = 0.0f, pr1 = 0.0f;
    const float inv = 0.0883883476483184f;  // 1/sqrt(128)

#pragma unroll 1
    for (int c = 0; c < 4; c++) {
        if (c > 0) __syncthreads();
        {
            const float4* sh = (const float4*)&g_Kh[(size_t)t * 65536 + (size_t)c * 16384];
            const float4* sl = (const float4*)&g_Kl[(size_t)t * 65536 + (size_t)c * 16384];
            float4* dh = (float4*)kfh;
            float4* dl = (float4*)kfl;
#pragma unroll
            for (int f = 0; f < 4; f++) {
                dh[tid + f * 512] = sh[tid + f * 512];
                dl[tid + f * 512] = sl[tid + f * 512];
            }
        }
        __syncthreads();

        float acc[4][4];
#pragma unroll
        for (int nt = 0; nt < 4; nt++)
#pragma unroll
            for (int e = 0; e < 4; e++) acc[nt][e] = 0.0f;

#pragma unroll 1
        for (int kk = 0; kk < 8; kk++) {
            uint4 AH = *(const uint4*)&qfh[((wband * 8 + kk) << 8) + lane * 8];
            uint4 AL = *(const uint4*)&qfl[((wband * 8 + kk) << 8) + lane * 8];
            uint32_t ah[4] = {AH.x, AH.y, AH.z, AH.w};
            uint32_t al[4] = {AL.x, AL.y, AL.z, AL.w};
#pragma unroll
            for (int nt = 0; nt < 4; nt++) {
                int tb = (((iq * 4 + nt) * 8 + kk) << 7) + lane * 4;
                uint2 BH = *(const uint2*)&kfh[tb];
                uint2 BL = *(const uint2*)&kfl[tb];
                mma_bf16(acc[nt], ah, BH.x, BH.y);   // hi*hi
                mma_bf16(acc[nt], ah, BL.x, BL.y);   // hi*lo
                mma_bf16(acc[nt], al, BH.x, BH.y);   // lo*hi
            }
        }

        // epilogue: tanh((score + c[m]) * inv) * s[i]
#pragma unroll
        for (int nt = 0; nt < 4; nt++) {
            int i0 = c * 128 + iq * 32 + nt * 8 + tg * 2;
            float sv0 = s_s[i0], sv1 = s_s[i0 + 1];
            pr0 = fmaf(ftanh((acc[nt][0] + c0) * inv), sv0, pr0);
            pr0 = fmaf(ftanh((acc[nt][1] + c0) * inv), sv1, pr0);
            pr1 = fmaf(ftanh((acc[nt][2] + c1) * inv), sv0, pr1);
            pr1 = fmaf(ftanh((acc[nt][3] + c1) * inv), sv1, pr1);
        }
    }

    pr0 += __shfl_xor_sync(0xffffffffu, pr0, 1);
    pr0 += __shfl_xor_sync(0xffffffffu, pr0, 2);
    pr1 += __shfl_xor_sync(0xffffffffu, pr1, 1);
    pr1 += __shfl_xor_sync(0xffffffffu, pr1, 2);
    if (tg == 0) {
        part[iq * 64 + m0 + g]     = pr0;
        part[iq * 64 + m0 + g + 8] = pr1;
    }
    __syncthreads();
    if (tid < 64)
        out[t * 1024 + mq * 64 + tid] =
            ftanh(part[tid] + part[64 + tid] + part[128 + tid] + part[192 + tid]);
}

// ---------------------------------------------------------------------------
extern "C" void kernel_launch(void* const* d_in, const int* in_sizes, int n_in,
                              void* d_out, int out_size) {
    const float* obs      = (const float*)d_in[0];
    const float* prev_act = (const float*)d_in[1];
    const float* in_shift = (const float*)d_in[2];
    const float* in_scale = (const float*)d_in[3];
    const float* pe       = (const float*)d_in[4];
    const float* W_ih     = (const float*)d_in[5];
    const float* b_ih     = (const float*)d_in[6];
    const float* W_hh     = (const float*)d_in[7];
    const float* b_hh     = (const float*)d_in[8];
    const float* Wq       = (const float*)d_in[9];
    const float* bq       = (const float*)d_in[10];
    const float* Wk       = (const float*)d_in[11];
    const float* bk       = (const float*)d_in[12];
    float* out = (float*)d_out;

    cudaFuncSetAttribute(attn_kernel, cudaFuncAttributeMaxDynamicSharedMemorySize,
                         ATTN_SMEM);
    cudaFuncSetAttribute(lstm_kernel, cudaFuncAttributeMaxDynamicSharedMemorySize,
                         LSTM_SMEM);

    setup_kernel<<<512, 256>>>(obs, prev_act, in_shift, in_scale,
                               W_ih, b_ih, b_hh, pe, Wq, bq, W_hh);
    q2_kernel<<<512, 256>>>(Wk, bk);
    lstm_kernel<<<128, 512, LSTM_SMEM>>>();
    dim3 ga(16, 256);
    attn_kernel<<<ga, 512, ATTN_SMEM>>>(out);
}